// round 13
// baseline (speedup 1.0000x reference)
#include <cuda_runtime.h>
#include <mma.h>
#include <math.h>

using namespace nvcuda;

// Problem constants
#define BB 2
#define NN 2048
#define CC 512
#define HH 8
#define DH 64
#define WW 64
#define RR 8
#define NG 32
#define M3 1536
#define MROWS 4096
#define LORA_SCALE 0.25f

// -------- scratch (device globals; proven clean) --------
__device__ float g_wqkv_eff[CC * M3];
__device__ float g_wout_eff[CC * CC];
__device__ float g_qkv[(size_t)MROWS * M3];
__device__ float g_attn[(size_t)MROWS * CC];

// ================= effective-weight fold (clean) ==========================
__global__ void eff_qkv_kernel(const float* __restrict__ w,
                               const float* __restrict__ la,
                               const float* __restrict__ lb) {
    int idx = blockIdx.x * blockDim.x + threadIdx.x;
    if (idx >= CC * M3) return;
    int c = idx / M3;
    int n = idx % M3;
    float s = 0.f;
#pragma unroll
    for (int r = 0; r < RR; r++) s += la[c * RR + r] * lb[r * M3 + n];
    g_wqkv_eff[idx] = w[idx] + LORA_SCALE * s;
}

__global__ void eff_out_kernel(const float* __restrict__ w,
                               const float* __restrict__ la,
                               const float* __restrict__ lb) {
    int idx = blockIdx.x * blockDim.x + threadIdx.x;
    if (idx >= CC * CC) return;
    int c = idx / CC;
    int n = idx % CC;
    float s = 0.f;
#pragma unroll
    for (int r = 0; r < RR; r++) s += la[c * RR + r] * lb[r * CC + n];
    g_wout_eff[idx] = w[idx] + LORA_SCALE * s;
}

// ================= wmma tf32 GEMM v2 ======================================
// C[M,N] = A[M,K] @ B[K,N]. Block tile 128x128x16, 256 thr = 8 warps (2m x 4n),
// warp tile 64x32 via 4x2 wmma 16x16x8 tf32 fragments. Double-buffered smem,
// gmem->reg prefetch. Template __device__ body + plain __global__ wrappers
// (the only structure proven to avoid the 128MiB local-pool trip).
template <int N, int K>
__device__ __forceinline__ void wmma_gemm_body2(const float* __restrict__ A,
                                                const float* __restrict__ Bm,
                                                float* __restrict__ C) {
    __shared__ __align__(16) float As[2][128][20];   // row-major [m][k], ldm 20
    __shared__ __align__(16) float Bs[2][16][132];   // row-major [k][n], ldm 132

    const int tid = threadIdx.x;
    const int wid = tid >> 5;
    const int wm = wid >> 2;          // 0..1 -> m offset wm*64
    const int wn = wid & 3;           // 0..3 -> n offset wn*32
    const int bm = blockIdx.y * 128, bn = blockIdx.x * 128;

    wmma::fragment<wmma::accumulator, 16, 16, 8, float> acc[4][2];
#pragma unroll
    for (int mi = 0; mi < 4; mi++)
#pragma unroll
        for (int ni = 0; ni < 2; ni++) wmma::fill_fragment(acc[mi][ni], 0.f);

    // copy indices: A tile 128x16 = 512 f4, B tile 16x128 = 512 f4; 2 each/thread
    const int ar0 = tid >> 2, ac4 = tid & 3;
    const int ar1 = (tid + 256) >> 2;
    const int bk0 = tid >> 5, bnc = (tid & 31) * 4;  // B rows bk0, bk0+8

    auto stage = [&](int buf, float4 a0, float4 a1, float4 b0, float4 b1) {
        As[buf][ar0][ac4 * 4 + 0] = wmma::__float_to_tf32(a0.x);
        As[buf][ar0][ac4 * 4 + 1] = wmma::__float_to_tf32(a0.y);
        As[buf][ar0][ac4 * 4 + 2] = wmma::__float_to_tf32(a0.z);
        As[buf][ar0][ac4 * 4 + 3] = wmma::__float_to_tf32(a0.w);
        As[buf][ar1][ac4 * 4 + 0] = wmma::__float_to_tf32(a1.x);
        As[buf][ar1][ac4 * 4 + 1] = wmma::__float_to_tf32(a1.y);
        As[buf][ar1][ac4 * 4 + 2] = wmma::__float_to_tf32(a1.z);
        As[buf][ar1][ac4 * 4 + 3] = wmma::__float_to_tf32(a1.w);
        Bs[buf][bk0][bnc + 0] = wmma::__float_to_tf32(b0.x);
        Bs[buf][bk0][bnc + 1] = wmma::__float_to_tf32(b0.y);
        Bs[buf][bk0][bnc + 2] = wmma::__float_to_tf32(b0.z);
        Bs[buf][bk0][bnc + 3] = wmma::__float_to_tf32(b0.w);
        Bs[buf][bk0 + 8][bnc + 0] = wmma::__float_to_tf32(b1.x);
        Bs[buf][bk0 + 8][bnc + 1] = wmma::__float_to_tf32(b1.y);
        Bs[buf][bk0 + 8][bnc + 2] = wmma::__float_to_tf32(b1.z);
        Bs[buf][bk0 + 8][bnc + 3] = wmma::__float_to_tf32(b1.w);
    };

    // prologue: tile 0 -> buffer 0
    {
        float4 a0 = *(const float4*)(A + (size_t)(bm + ar0) * K + ac4 * 4);
        float4 a1 = *(const float4*)(A + (size_t)(bm + ar1) * K + ac4 * 4);
        float4 b0 = *(const float4*)(Bm + (size_t)bk0 * N + bn + bnc);
        float4 b1 = *(const float4*)(Bm + (size_t)(bk0 + 8) * N + bn + bnc);
        stage(0, a0, a1, b0, b1);
    }
    __syncthreads();

    const int NT = K / 16;
    for (int t = 0; t < NT; t++) {
        const int s = t & 1;
        float4 a0, a1, b0, b1;
        if (t + 1 < NT) {
            const int k0 = (t + 1) * 16;
            a0 = *(const float4*)(A + (size_t)(bm + ar0) * K + k0 + ac4 * 4);
            a1 = *(const float4*)(A + (size_t)(bm + ar1) * K + k0 + ac4 * 4);
            b0 = *(const float4*)(Bm + (size_t)(k0 + bk0) * N + bn + bnc);
            b1 = *(const float4*)(Bm + (size_t)(k0 + bk0 + 8) * N + bn + bnc);
        }

#pragma unroll
        for (int kb = 0; kb < 16; kb += 8) {
            wmma::fragment<wmma::matrix_a, 16, 16, 8, wmma::precision::tf32, wmma::row_major> af[4];
            wmma::fragment<wmma::matrix_b, 16, 16, 8, wmma::precision::tf32, wmma::row_major> bf[2];
#pragma unroll
            for (int mi = 0; mi < 4; mi++)
                wmma::load_matrix_sync(af[mi], &As[s][wm * 64 + mi * 16][kb], 20);
#pragma unroll
            for (int ni = 0; ni < 2; ni++)
                wmma::load_matrix_sync(bf[ni], &Bs[s][kb][wn * 32 + ni * 16], 132);
#pragma unroll
            for (int mi = 0; mi < 4; mi++)
#pragma unroll
                for (int ni = 0; ni < 2; ni++)
                    wmma::mma_sync(acc[mi][ni], af[mi], bf[ni], acc[mi][ni]);
        }

        if (t + 1 < NT) stage(s ^ 1, a0, a1, b0, b1);
        __syncthreads();
    }

#pragma unroll
    for (int mi = 0; mi < 4; mi++)
#pragma unroll
        for (int ni = 0; ni < 2; ni++)
            wmma::store_matrix_sync(C + (size_t)(bm + wm * 64 + mi * 16) * N
                                      + bn + wn * 32 + ni * 16,
                                    acc[mi][ni], N, wmma::mem_row_major);
}

// plain, non-template __global__ wrappers (clean pattern)
__global__ __launch_bounds__(256) void wmma_qkv_kernel(const float* __restrict__ x) {
    wmma_gemm_body2<M3, CC>(x, g_wqkv_eff, g_qkv);
}

__global__ __launch_bounds__(256) void wmma_out_kernel(float* __restrict__ out) {
    wmma_gemm_body2<CC, CC>(g_attn, g_wout_eff, out);
}

// bias add for the out projection (out += b_out per column)
__global__ void bias_add_kernel(float* __restrict__ out, const float* __restrict__ bias) {
    int idx = blockIdx.x * blockDim.x + threadIdx.x;   // float4 index
    if (idx >= MROWS * CC / 4) return;
    float4 v = ((float4*)out)[idx];
    const float4 bv = ((const float4*)bias)[idx & (CC / 4 - 1)];
    v.x += bv.x; v.y += bv.y; v.z += bv.z; v.w += bv.w;
    ((float4*)out)[idx] = v;
}

// ================= attention v3 (R11 verbatim, clean, 71us) ===============
__device__ __forceinline__ float warp_max(float v) {
    v = fmaxf(v, __shfl_xor_sync(0xffffffffu, v, 16));
    v = fmaxf(v, __shfl_xor_sync(0xffffffffu, v, 8));
    v = fmaxf(v, __shfl_xor_sync(0xffffffffu, v, 4));
    v = fmaxf(v, __shfl_xor_sync(0xffffffffu, v, 2));
    v = fmaxf(v, __shfl_xor_sync(0xffffffffu, v, 1));
    return v;
}
__device__ __forceinline__ float warp_sum(float v) {
    v += __shfl_xor_sync(0xffffffffu, v, 16);
    v += __shfl_xor_sync(0xffffffffu, v, 8);
    v += __shfl_xor_sync(0xffffffffu, v, 4);
    v += __shfl_xor_sync(0xffffffffu, v, 2);
    v += __shfl_xor_sync(0xffffffffu, v, 1);
    return v;
}

__global__ __launch_bounds__(256) void attn3_kernel() {
    __shared__ float4 Qs[32][16];  // plain: reads broadcast
    __shared__ float4 Ks[32][16];  // swizzled: phys c4 = c4 ^ (r&15)
    __shared__ float4 Vs[32][16];  // swizzled

    const int tid = threadIdx.x;
    const int warp = tid >> 5, lane = tid & 31;
    const int qt = blockIdx.x * 32;
    const int h = blockIdx.y, b = blockIdx.z;
    const int q0 = warp * 4;       // 4 queries per warp

    // stage Q (pre-scaled); 512 float4 over 256 threads
    for (int t = tid; t < 512; t += 256) {
        int r = t >> 4, c4 = t & 15;
        float4 v = *((const float4*)(g_qkv + ((size_t)(b * NN + qt + r) * 3 + 0) * CC + h * DH) + c4);
        v.x *= 0.125f; v.y *= 0.125f; v.z *= 0.125f; v.w *= 0.125f;
        Qs[r][c4] = v;
    }

    float m[4], l[4];
    float2 o[4], oL[4];
#pragma unroll
    for (int q = 0; q < 4; q++) {
        m[q] = -1e30f; l[q] = 0.f;
        o[q] = make_float2(0.f, 0.f);
    }

    // ---------------- LOCAL phase ----------------
    const int jt_start = (qt >= 64) ? qt - 64 : 0;
    for (int jt = jt_start; jt <= qt; jt += 32) {
        __syncthreads();
        for (int t = tid; t < 512; t += 256) {
            int r = t >> 4, c4 = t & 15;
            size_t row3 = (size_t)(b * NN + jt + r) * 3;
            int pc = c4 ^ (r & 15);
            Ks[r][pc] = *((const float4*)(g_qkv + (row3 + 1) * CC + h * DH) + c4);
            Vs[r][pc] = *((const float4*)(g_qkv + (row3 + 2) * CC + h * DH) + c4);
        }
        __syncthreads();

        float s[4];
#pragma unroll
        for (int q = 0; q < 4; q++) s[q] = 0.f;
#pragma unroll
        for (int c4 = 0; c4 < 16; c4++) {
            float4 k4 = Ks[lane][c4 ^ (lane & 15)];
#pragma unroll
            for (int q = 0; q < 4; q++) {
                float4 q4 = Qs[q0 + q][c4];
                s[q] += q4.x * k4.x + q4.y * k4.y + q4.z * k4.z + q4.w * k4.w;
            }
        }
        const int j = jt + lane;
        float p[4];
#pragma unroll
        for (int q = 0; q < 4; q++) {
            const int i = qt + q0 + q;
            const bool valid = (j <= i) && (i - j <= WW);
            const float sv = valid ? s[q] : -1e30f;
            const float tmax = warp_max(sv);
            const float mn = fmaxf(m[q], tmax);
            const float corr = __expf(m[q] - mn);
            p[q] = valid ? __expf(s[q] - mn) : 0.f;
            const float ts = warp_sum(p[q]);
            l[q] = l[q] * corr + ts;
            o[q].x *= corr; o[q].y *= corr;
            m[q] = mn;
        }
        const float2* vrows = (const float2*)Vs;
#pragma unroll 8
        for (int jj = 0; jj < 32; jj++) {
            float2 v2 = vrows[jj * 32 + ((((lane >> 1) ^ (jj & 15)) << 1) | (lane & 1))];
#pragma unroll
            for (int q = 0; q < 4; q++) {
                float pj = __shfl_sync(0xffffffffu, p[q], jj);
                o[q].x += pj * v2.x;
                o[q].y += pj * v2.y;
            }
        }
    }
#pragma unroll
    for (int q = 0; q < 4; q++) {
        oL[q].x = o[q].x / l[q];
        oL[q].y = o[q].y / l[q];
        l[q] = 0.f;
        o[q] = make_float2(0.f, 0.f);
    }

    // ---------------- GLOBAL phase (32 strided keys, unmasked) -----------
    __syncthreads();
    for (int t = tid; t < 512; t += 256) {
        int r = t >> 4, c4 = t & 15;
        size_t row3 = (size_t)(b * NN + r * WW) * 3;
        int pc = c4 ^ (r & 15);
        Ks[r][pc] = *((const float4*)(g_qkv + (row3 + 1) * CC + h * DH) + c4);
        Vs[r][pc] = *((const float4*)(g_qkv + (row3 + 2) * CC + h * DH) + c4);
    }
    __syncthreads();
    {
        float s[4];
#pragma unroll
        for (int q = 0; q < 4; q++) s[q] = 0.f;
#pragma unroll
        for (int c4 = 0; c4 < 16; c4++) {
            float4 k4 = Ks[lane][c4 ^ (lane & 15)];
#pragma unroll
            for (int q = 0; q < 4; q++) {
                float4 q4 = Qs[q0 + q][c4];
                s[q] += q4.x * k4.x + q4.y * k4.y + q4.z * k4.z + q4.w * k4.w;
            }
        }
        float p[4];
#pragma unroll
        for (int q = 0; q < 4; q++) {
            const float mn = warp_max(s[q]);
            p[q] = __expf(s[q] - mn);
            l[q] = warp_sum(p[q]);
        }
        const float2* vrows = (const float2*)Vs;
#pragma unroll 8
        for (int jj = 0; jj < 32; jj++) {
            float2 v2 = vrows[jj * 32 + ((((lane >> 1) ^ (jj & 15)) << 1) | (lane & 1))];
#pragma unroll
            for (int q = 0; q < 4; q++) {
                float pj = __shfl_sync(0xffffffffu, p[q], jj);
                o[q].x += pj * v2.x;
                o[q].y += pj * v2.y;
            }
        }
    }

    // out = local + global, store
#pragma unroll
    for (int q = 0; q < 4; q++) {
        const int i = qt + q0 + q;
        float2 r;
        r.x = oL[q].x + o[q].x / l[q];
        r.y = oL[q].y + o[q].y / l[q];
        ((float2*)(g_attn + (size_t)(b * NN + i) * CC + h * DH))[lane] = r;
    }
}

// ================= launch =================================================
extern "C" void kernel_launch(void* const* d_in, const int* in_sizes, int n_in,
                              void* d_out, int out_size) {
    const float* x       = (const float*)d_in[0];
    const float* w_qkv   = (const float*)d_in[1];
    const float* lA_qkv  = (const float*)d_in[2];
    const float* lB_qkv  = (const float*)d_in[3];
    const float* w_out   = (const float*)d_in[4];
    const float* b_out   = (const float*)d_in[5];
    const float* lA_out  = (const float*)d_in[6];
    const float* lB_out  = (const float*)d_in[7];
    float* out = (float*)d_out;

    // 1) fold LoRA into effective weights
    eff_qkv_kernel<<<(CC * M3 + 255) / 256, 256>>>(w_qkv, lA_qkv, lB_qkv);
    eff_out_kernel<<<(CC * CC + 255) / 256, 256>>>(w_out, lA_out, lB_out);

    // 2) qkv = x @ w_qkv_eff : 4096 x 1536 x 512 (wmma tf32 v2)
    wmma_qkv_kernel<<<dim3(M3 / 128, MROWS / 128), 256>>>(x);

    // 3) attention: tiled, 32 queries/block (clean, 71us)
    attn3_kernel<<<dim3(NN / 32, HH, BB), 256>>>();

    // 4) out = attn @ w_out_eff + b_out : 4096 x 512 x 512 (wmma tf32 v2)
    wmma_out_kernel<<<dim3(CC / 128, MROWS / 128), 256>>>(out);
    bias_add_kernel<<<(MROWS * CC / 4 + 255) / 256, 256>>>(out, b_out);
}

// round 14
// speedup vs baseline: 1.0446x; 1.0446x over previous
#include <cuda_runtime.h>
#include <cuda_pipeline.h>
#include <mma.h>
#include <math.h>

using namespace nvcuda;

// Problem constants
#define BB 2
#define NN 2048
#define CC 512
#define HH 8
#define DH 64
#define WW 64
#define RR 8
#define NG 32
#define M3 1536
#define MROWS 4096
#define LORA_SCALE 0.25f

// -------- scratch (device globals; proven clean) --------
__device__ float g_wqkv_eff[CC * M3];
__device__ float g_wout_eff[CC * CC];
__device__ float g_x[(size_t)MROWS * CC];      // tf32-rounded x
__device__ float g_qkv[(size_t)MROWS * M3];
__device__ float g_attn[(size_t)MROWS * CC];   // tf32-rounded attn out

// ================= producers: tf32-rounded operands =======================
__global__ void eff_qkv_kernel(const float* __restrict__ w,
                               const float* __restrict__ la,
                               const float* __restrict__ lb) {
    int idx = blockIdx.x * blockDim.x + threadIdx.x;
    if (idx >= CC * M3) return;
    int c = idx / M3;
    int n = idx % M3;
    float s = 0.f;
#pragma unroll
    for (int r = 0; r < RR; r++) s += la[c * RR + r] * lb[r * M3 + n];
    g_wqkv_eff[idx] = wmma::__float_to_tf32(w[idx] + LORA_SCALE * s);
}

__global__ void eff_out_kernel(const float* __restrict__ w,
                               const float* __restrict__ la,
                               const float* __restrict__ lb) {
    int idx = blockIdx.x * blockDim.x + threadIdx.x;
    if (idx >= CC * CC) return;
    int c = idx / CC;
    int n = idx % CC;
    float s = 0.f;
#pragma unroll
    for (int r = 0; r < RR; r++) s += la[c * RR + r] * lb[r * CC + n];
    g_wout_eff[idx] = wmma::__float_to_tf32(w[idx] + LORA_SCALE * s);
}

__global__ void cvt_x_kernel(const float* __restrict__ x) {
    int idx = blockIdx.x * blockDim.x + threadIdx.x;   // float4 index
    if (idx >= MROWS * CC / 4) return;
    float4 v = ((const float4*)x)[idx];
    v.x = wmma::__float_to_tf32(v.x);
    v.y = wmma::__float_to_tf32(v.y);
    v.z = wmma::__float_to_tf32(v.z);
    v.w = wmma::__float_to_tf32(v.w);
    ((float4*)g_x)[idx] = v;
}

// ================= wmma tf32 GEMM v3: cp.async pipelined ==================
// C[M,N] = A[M,K] @ B[K,N]. Inputs pre-rounded to tf32 bit patterns.
// Block tile 128x128x16, 256 thr = 8 warps (2m x 4n), warp tile 64x32 via
// 4x2 wmma 16x16x8 frags. 2-stage smem pipeline via __pipeline_memcpy_async
// (no staging registers, no cvt in the hot loop).
// Template __device__ body + plain __global__ wrappers (clean structure).
template <int N, int K>
__device__ __forceinline__ void wmma_gemm_body3(const float* __restrict__ A,
                                                const float* __restrict__ Bm,
                                                float* __restrict__ C) {
    __shared__ __align__(16) float As[2][128][20];   // [m][k], ldm 20 (80B rows)
    __shared__ __align__(16) float Bs[2][16][132];   // [k][n], ldm 132 (528B rows)

    const int tid = threadIdx.x;
    const int wid = tid >> 5;
    const int wm = wid >> 2;          // 0..1 -> m offset wm*64
    const int wn = wid & 3;           // 0..3 -> n offset wn*32
    const int bm = blockIdx.y * 128, bn = blockIdx.x * 128;

    wmma::fragment<wmma::accumulator, 16, 16, 8, float> acc[4][2];
#pragma unroll
    for (int mi = 0; mi < 4; mi++)
#pragma unroll
        for (int ni = 0; ni < 2; ni++) wmma::fill_fragment(acc[mi][ni], 0.f);

    // copy indices: A tile 128x16 = 512 f4, B tile 16x128 = 512 f4; 2 each/thread
    const int ar0 = tid >> 2, ac4 = (tid & 3) * 4;     // A rows ar0, ar1
    const int ar1 = (tid + 256) >> 2;
    const int bk0 = tid >> 5, bnc = (tid & 31) * 4;    // B rows bk0, bk0+8

    auto issue = [&](int buf, int k0) {
        __pipeline_memcpy_async(&As[buf][ar0][ac4],
                                A + (size_t)(bm + ar0) * K + k0 + ac4, 16);
        __pipeline_memcpy_async(&As[buf][ar1][ac4],
                                A + (size_t)(bm + ar1) * K + k0 + ac4, 16);
        __pipeline_memcpy_async(&Bs[buf][bk0][bnc],
                                Bm + (size_t)(k0 + bk0) * N + bn + bnc, 16);
        __pipeline_memcpy_async(&Bs[buf][bk0 + 8][bnc],
                                Bm + (size_t)(k0 + bk0 + 8) * N + bn + bnc, 16);
    };

    issue(0, 0);
    __pipeline_commit();

    const int NT = K / 16;
    for (int t = 0; t < NT; t++) {
        const int s = t & 1;
        if (t + 1 < NT) {
            issue(s ^ 1, (t + 1) * 16);   // safe: buf s^1 freed by sync (b) of t-1
            __pipeline_commit();
            __pipeline_wait_prior(1);     // tile t's copies (this thread) done
        } else {
            __pipeline_wait_prior(0);
        }
        __syncthreads();                  // (a) tile t visible to all warps

#pragma unroll
        for (int kb = 0; kb < 16; kb += 8) {
            wmma::fragment<wmma::matrix_a, 16, 16, 8, wmma::precision::tf32, wmma::row_major> af[4];
            wmma::fragment<wmma::matrix_b, 16, 16, 8, wmma::precision::tf32, wmma::row_major> bf[2];
#pragma unroll
            for (int mi = 0; mi < 4; mi++)
                wmma::load_matrix_sync(af[mi], &As[s][wm * 64 + mi * 16][kb], 20);
#pragma unroll
            for (int ni = 0; ni < 2; ni++)
                wmma::load_matrix_sync(bf[ni], &Bs[s][kb][wn * 32 + ni * 16], 132);
#pragma unroll
            for (int mi = 0; mi < 4; mi++)
#pragma unroll
                for (int ni = 0; ni < 2; ni++)
                    wmma::mma_sync(acc[mi][ni], af[mi], bf[ni], acc[mi][ni]);
        }
        __syncthreads();                  // (b) buf s fully consumed
    }

#pragma unroll
    for (int mi = 0; mi < 4; mi++)
#pragma unroll
        for (int ni = 0; ni < 2; ni++)
            wmma::store_matrix_sync(C + (size_t)(bm + wm * 64 + mi * 16) * N
                                      + bn + wn * 32 + ni * 16,
                                    acc[mi][ni], N, wmma::mem_row_major);
}

// plain, non-template __global__ wrappers (clean pattern)
__global__ __launch_bounds__(256) void wmma_qkv_kernel() {
    wmma_gemm_body3<M3, CC>(g_x, g_wqkv_eff, g_qkv);
}

__global__ __launch_bounds__(256) void wmma_out_kernel(float* __restrict__ out) {
    wmma_gemm_body3<CC, CC>(g_attn, g_wout_eff, out);
}

// bias add for the out projection (out += b_out per column)
__global__ void bias_add_kernel(float* __restrict__ out, const float* __restrict__ bias) {
    int idx = blockIdx.x * blockDim.x + threadIdx.x;   // float4 index
    if (idx >= MROWS * CC / 4) return;
    float4 v = ((float4*)out)[idx];
    const float4 bv = ((const float4*)bias)[idx & (CC / 4 - 1)];
    v.x += bv.x; v.y += bv.y; v.z += bv.z; v.w += bv.w;
    ((float4*)out)[idx] = v;
}

// ================= attention v3 (clean, 71us; tf32-rounded output) ========
__device__ __forceinline__ float warp_max(float v) {
    v = fmaxf(v, __shfl_xor_sync(0xffffffffu, v, 16));
    v = fmaxf(v, __shfl_xor_sync(0xffffffffu, v, 8));
    v = fmaxf(v, __shfl_xor_sync(0xffffffffu, v, 4));
    v = fmaxf(v, __shfl_xor_sync(0xffffffffu, v, 2));
    v = fmaxf(v, __shfl_xor_sync(0xffffffffu, v, 1));
    return v;
}
__device__ __forceinline__ float warp_sum(float v) {
    v += __shfl_xor_sync(0xffffffffu, v, 16);
    v += __shfl_xor_sync(0xffffffffu, v, 8);
    v += __shfl_xor_sync(0xffffffffu, v, 4);
    v += __shfl_xor_sync(0xffffffffu, v, 2);
    v += __shfl_xor_sync(0xffffffffu, v, 1);
    return v;
}

__global__ __launch_bounds__(256) void attn3_kernel() {
    __shared__ float4 Qs[32][16];  // plain: reads broadcast
    __shared__ float4 Ks[32][16];  // swizzled: phys c4 = c4 ^ (r&15)
    __shared__ float4 Vs[32][16];  // swizzled

    const int tid = threadIdx.x;
    const int warp = tid >> 5, lane = tid & 31;
    const int qt = blockIdx.x * 32;
    const int h = blockIdx.y, b = blockIdx.z;
    const int q0 = warp * 4;       // 4 queries per warp

    // stage Q (pre-scaled); 512 float4 over 256 threads
    for (int t = tid; t < 512; t += 256) {
        int r = t >> 4, c4 = t & 15;
        float4 v = *((const float4*)(g_qkv + ((size_t)(b * NN + qt + r) * 3 + 0) * CC + h * DH) + c4);
        v.x *= 0.125f; v.y *= 0.125f; v.z *= 0.125f; v.w *= 0.125f;
        Qs[r][c4] = v;
    }

    float m[4], l[4];
    float2 o[4], oL[4];
#pragma unroll
    for (int q = 0; q < 4; q++) {
        m[q] = -1e30f; l[q] = 0.f;
        o[q] = make_float2(0.f, 0.f);
    }

    // ---------------- LOCAL phase ----------------
    const int jt_start = (qt >= 64) ? qt - 64 : 0;
    for (int jt = jt_start; jt <= qt; jt += 32) {
        __syncthreads();
        for (int t = tid; t < 512; t += 256) {
            int r = t >> 4, c4 = t & 15;
            size_t row3 = (size_t)(b * NN + jt + r) * 3;
            int pc = c4 ^ (r & 15);
            Ks[r][pc] = *((const float4*)(g_qkv + (row3 + 1) * CC + h * DH) + c4);
            Vs[r][pc] = *((const float4*)(g_qkv + (row3 + 2) * CC + h * DH) + c4);
        }
        __syncthreads();

        float s[4];
#pragma unroll
        for (int q = 0; q < 4; q++) s[q] = 0.f;
#pragma unroll
        for (int c4 = 0; c4 < 16; c4++) {
            float4 k4 = Ks[lane][c4 ^ (lane & 15)];
#pragma unroll
            for (int q = 0; q < 4; q++) {
                float4 q4 = Qs[q0 + q][c4];
                s[q] += q4.x * k4.x + q4.y * k4.y + q4.z * k4.z + q4.w * k4.w;
            }
        }
        const int j = jt + lane;
        float p[4];
#pragma unroll
        for (int q = 0; q < 4; q++) {
            const int i = qt + q0 + q;
            const bool valid = (j <= i) && (i - j <= WW);
            const float sv = valid ? s[q] : -1e30f;
            const float tmax = warp_max(sv);
            const float mn = fmaxf(m[q], tmax);
            const float corr = __expf(m[q] - mn);
            p[q] = valid ? __expf(s[q] - mn) : 0.f;
            const float ts = warp_sum(p[q]);
            l[q] = l[q] * corr + ts;
            o[q].x *= corr; o[q].y *= corr;
            m[q] = mn;
        }
        const float2* vrows = (const float2*)Vs;
#pragma unroll 8
        for (int jj = 0; jj < 32; jj++) {
            float2 v2 = vrows[jj * 32 + ((((lane >> 1) ^ (jj & 15)) << 1) | (lane & 1))];
#pragma unroll
            for (int q = 0; q < 4; q++) {
                float pj = __shfl_sync(0xffffffffu, p[q], jj);
                o[q].x += pj * v2.x;
                o[q].y += pj * v2.y;
            }
        }
    }
#pragma unroll
    for (int q = 0; q < 4; q++) {
        oL[q].x = o[q].x / l[q];
        oL[q].y = o[q].y / l[q];
        l[q] = 0.f;
        o[q] = make_float2(0.f, 0.f);
    }

    // ---------------- GLOBAL phase (32 strided keys, unmasked) -----------
    __syncthreads();
    for (int t = tid; t < 512; t += 256) {
        int r = t >> 4, c4 = t & 15;
        size_t row3 = (size_t)(b * NN + r * WW) * 3;
        int pc = c4 ^ (r & 15);
        Ks[r][pc] = *((const float4*)(g_qkv + (row3 + 1) * CC + h * DH) + c4);
        Vs[r][pc] = *((const float4*)(g_qkv + (row3 + 2) * CC + h * DH) + c4);
    }
    __syncthreads();
    {
        float s[4];
#pragma unroll
        for (int q = 0; q < 4; q++) s[q] = 0.f;
#pragma unroll
        for (int c4 = 0; c4 < 16; c4++) {
            float4 k4 = Ks[lane][c4 ^ (lane & 15)];
#pragma unroll
            for (int q = 0; q < 4; q++) {
                float4 q4 = Qs[q0 + q][c4];
                s[q] += q4.x * k4.x + q4.y * k4.y + q4.z * k4.z + q4.w * k4.w;
            }
        }
        float p[4];
#pragma unroll
        for (int q = 0; q < 4; q++) {
            const float mn = warp_max(s[q]);
            p[q] = __expf(s[q] - mn);
            l[q] = warp_sum(p[q]);
        }
        const float2* vrows = (const float2*)Vs;
#pragma unroll 8
        for (int jj = 0; jj < 32; jj++) {
            float2 v2 = vrows[jj * 32 + ((((lane >> 1) ^ (jj & 15)) << 1) | (lane & 1))];
#pragma unroll
            for (int q = 0; q < 4; q++) {
                float pj = __shfl_sync(0xffffffffu, p[q], jj);
                o[q].x += pj * v2.x;
                o[q].y += pj * v2.y;
            }
        }
    }

    // out = local + global, store tf32-rounded (A operand of out-proj GEMM)
#pragma unroll
    for (int q = 0; q < 4; q++) {
        const int i = qt + q0 + q;
        float2 r;
        r.x = wmma::__float_to_tf32(oL[q].x + o[q].x / l[q]);
        r.y = wmma::__float_to_tf32(oL[q].y + o[q].y / l[q]);
        ((float2*)(g_attn + (size_t)(b * NN + i) * CC + h * DH))[lane] = r;
    }
}

// ================= launch =================================================
extern "C" void kernel_launch(void* const* d_in, const int* in_sizes, int n_in,
                              void* d_out, int out_size) {
    const float* x       = (const float*)d_in[0];
    const float* w_qkv   = (const float*)d_in[1];
    const float* lA_qkv  = (const float*)d_in[2];
    const float* lB_qkv  = (const float*)d_in[3];
    const float* w_out   = (const float*)d_in[4];
    const float* b_out   = (const float*)d_in[5];
    const float* lA_out  = (const float*)d_in[6];
    const float* lB_out  = (const float*)d_in[7];
    float* out = (float*)d_out;

    // 1) fold LoRA into effective weights (tf32-rounded) + round x
    eff_qkv_kernel<<<(CC * M3 + 255) / 256, 256>>>(w_qkv, lA_qkv, lB_qkv);
    eff_out_kernel<<<(CC * CC + 255) / 256, 256>>>(w_out, lA_out, lB_out);
    cvt_x_kernel<<<(MROWS * CC / 4 + 255) / 256, 256>>>(x);

    // 2) qkv = x @ w_qkv_eff : 4096 x 1536 x 512 (wmma tf32 v3, cp.async)
    wmma_qkv_kernel<<<dim3(M3 / 128, MROWS / 128), 256>>>();

    // 3) attention: tiled, 32 queries/block (clean, 71us)
    attn3_kernel<<<dim3(NN / 32, HH, BB), 256>>>();

    // 4) out = attn @ w_out_eff + b_out : 4096 x 512 x 512 (wmma tf32 v3)
    wmma_out_kernel<<<dim3(CC / 128, MROWS / 128), 256>>>(out);
    bias_add_kernel<<<(MROWS * CC / 4 + 255) / 256, 256>>>(out, b_out);
}